// round 4
// baseline (speedup 1.0000x reference)
#include <cuda_runtime.h>
#include <cuda_bf16.h>
#include <cstdint>

#define M_B 4096
#define N_H 16384
#define K_D 1024
#define KSEL 32
#define CANDCAP 512
#define CAND_SMEM 4096
#define SEL_T 512

// ---------------- scratch (device globals; no allocation) ----------------
__device__ __nv_bfloat16 g_xb[(size_t)M_B * K_D];    // 8MB   x in bf16
__device__ __nv_bfloat16 g_wb[(size_t)N_H * K_D];    // 33MB  W_enc in bf16
__device__ __nv_bfloat16 g_encbf[(size_t)M_B * N_H]; // 134MB approx enc (bf16)
__device__ float g_Wt[(size_t)N_H * K_D];            // 64MB  W_dec^T

// ======================= helpers =======================
__device__ __forceinline__ uint32_t smem_u32(const void* p) {
    uint32_t a;
    asm("{ .reg .u64 t; cvta.to.shared.u64 t, %1; cvt.u32.u64 %0, t; }" : "=r"(a) : "l"(p));
    return a;
}
__device__ __forceinline__ void cp16(uint32_t dst, const void* src) {
    asm volatile("cp.async.cg.shared.global [%0], [%1], 16;" :: "r"(dst), "l"(src) : "memory");
}
__device__ __forceinline__ void cp_commit() {
    asm volatile("cp.async.commit_group;" ::: "memory");
}
template <int N> __device__ __forceinline__ void cp_wait() {
    asm volatile("cp.async.wait_group %0;" :: "n"(N) : "memory");
}
__device__ __forceinline__ void ldsm4(uint32_t& r0, uint32_t& r1, uint32_t& r2,
                                      uint32_t& r3, uint32_t a) {
    asm volatile("ldmatrix.sync.aligned.m8n8.x4.shared.b16 {%0,%1,%2,%3}, [%4];"
                 : "=r"(r0), "=r"(r1), "=r"(r2), "=r"(r3) : "r"(a));
}
__device__ __forceinline__ void mma16816(float* d, uint32_t a0, uint32_t a1,
                                         uint32_t a2, uint32_t a3,
                                         uint32_t b0, uint32_t b1) {
    asm volatile("mma.sync.aligned.m16n8k16.row.col.f32.bf16.bf16.f32 "
                 "{%0,%1,%2,%3}, {%4,%5,%6,%7}, {%8,%9}, {%0,%1,%2,%3};"
                 : "+f"(d[0]), "+f"(d[1]), "+f"(d[2]), "+f"(d[3])
                 : "r"(a0), "r"(a1), "r"(a2), "r"(a3), "r"(b0), "r"(b1));
}
#define SWZ(off) ((off) ^ (((off) >> 3) & 0x70))

template <int NT>
__device__ __forceinline__ unsigned brsum(unsigned v, unsigned* s_red) {
    const int tid = threadIdx.x;
#pragma unroll
    for (int o = 16; o; o >>= 1) v += __shfl_xor_sync(0xffffffffu, v, o);
    if ((tid & 31) == 0) s_red[tid >> 5] = v;
    __syncthreads();
    if (tid < 32) {
        unsigned t = (tid < NT / 32) ? s_red[tid] : 0u;
#pragma unroll
        for (int o = 16; o; o >>= 1) t += __shfl_xor_sync(0xffffffffu, t, o);
        if (tid == 0) s_red[0] = t;
    }
    __syncthreads();
    unsigned r = s_red[0];
    __syncthreads();
    return r;
}
template <int NT>
__device__ __forceinline__ unsigned brmax(unsigned v, unsigned* s_red) {
    const int tid = threadIdx.x;
#pragma unroll
    for (int o = 16; o; o >>= 1) v = max(v, __shfl_xor_sync(0xffffffffu, v, o));
    if ((tid & 31) == 0) s_red[tid >> 5] = v;
    __syncthreads();
    if (tid < 32) {
        unsigned t = (tid < NT / 32) ? s_red[tid] : 0u;
#pragma unroll
        for (int o = 16; o; o >>= 1) t = max(t, __shfl_xor_sync(0xffffffffu, t, o));
        if (tid == 0) s_red[0] = t;
    }
    __syncthreads();
    unsigned r = s_red[0];
    __syncthreads();
    return r;
}

// ======================================================================
// fp32 -> bf16 conversion
// ======================================================================
__global__ __launch_bounds__(256) void convert_kernel(const float* __restrict__ src,
                                                      __nv_bfloat16* __restrict__ dst) {
    const size_t g = (size_t)blockIdx.x * 256 + threadIdx.x;
    const float4 v = ((const float4*)src)[g];
    __nv_bfloat162 lo = __floats2bfloat162_rn(v.x, v.y);
    __nv_bfloat162 hi = __floats2bfloat162_rn(v.z, v.w);
    uint32_t a = *(uint32_t*)&lo, b = *(uint32_t*)&hi;
    ((uint2*)dst)[g] = make_uint2(a, b);
}

// ======================================================================
// Approx encoder GEMM (bf16 HMMA): C = x @ W^T + b, bf16 out.
// 128x128 tile, 3-stage cp.async ring, ONE syncthreads per K-tile,
// 2 CTAs/SM. 8 warps as 2(m) x 4(n), warp tile 64x32.
// ======================================================================
__global__ __launch_bounds__(256, 2) void enc_hmma_kernel(const float* __restrict__ bias,
                                                          __nv_bfloat16* __restrict__ C) {
    extern __shared__ __align__(1024) char smem[];   // 3 stages x 32KB
    const int tid = threadIdx.x;
    const int wid = tid >> 5, lane = tid & 31;
    const int bm = blockIdx.y * 128, bn = blockIdx.x * 128;
    const int wm = (wid >> 2) * 64, wn = (wid & 3) * 32;

    float acc[4][4][4];
#pragma unroll
    for (int i = 0; i < 4; i++)
#pragma unroll
        for (int j = 0; j < 4; j++)
#pragma unroll
            for (int q = 0; q < 4; q++) acc[i][j][q] = 0.f;

    const __nv_bfloat16* Abase = g_xb + (size_t)bm * K_D;
    const __nv_bfloat16* Bbase = g_wb + (size_t)bn * K_D;
    const uint32_t sbase = smem_u32(smem);

    // per-thread load coords (fixed across tiles)
    const int lrowA = tid >> 1;                  // 0..127
    const int lkbA = (tid & 1) * 4;              // 2 x 4 kb segments? -> 8 segs of 16B each row
    // Each thread loads 4 x 16B for A and 4 x 16B for B:
    // mapping: u = tid + i*256 ; row = u >> 3 ; kb = u & 7
#define LOAD_TILE(s, kt)                                                          \
    {                                                                             \
        const uint32_t sa = sbase + (s) * 32768;                                  \
        const __nv_bfloat16* Ag = Abase + (kt) * 64;                              \
        const __nv_bfloat16* Bg = Bbase + (kt) * 64;                              \
        _Pragma("unroll")                                                         \
        for (int i = 0; i < 4; i++) {                                             \
            int u = tid + i * 256, row = u >> 3, kb = u & 7;                      \
            cp16(sa + SWZ(row * 128 + kb * 16), Ag + (size_t)row * K_D + kb * 8); \
        }                                                                         \
        _Pragma("unroll")                                                         \
        for (int i = 0; i < 4; i++) {                                             \
            int u = tid + i * 256, row = u >> 3, kb = u & 7;                      \
            cp16(sa + 16384 + SWZ(row * 128 + kb * 16), Bg + (size_t)row * K_D + kb * 8); \
        }                                                                         \
        cp_commit();                                                              \
    }

    LOAD_TILE(0, 0);
    LOAD_TILE(1, 1);

    for (int kt = 0; kt < K_D / 64; ++kt) {
        cp_wait<1>();          // group kt complete (kt+1 may be in flight)
        __syncthreads();       // data visible to all; stage (kt+2)%3 reusable

        if (kt + 2 < K_D / 64) { LOAD_TILE((kt + 2) % 3, kt + 2); }
        else cp_commit();      // keep group count consistent

        const uint32_t sa = sbase + (kt % 3) * 32768;
        const uint32_t sb = sa + 16384;
#pragma unroll
        for (int ks = 0; ks < 4; ks++) {
            uint32_t ra[4][4], rb[2][4];
#pragma unroll
            for (int mi = 0; mi < 4; mi++) {
                const int row = wm + mi * 16 + (lane & 15);
                const int koff = ks * 32 + ((lane >> 4) << 4);
                ldsm4(ra[mi][0], ra[mi][1], ra[mi][2], ra[mi][3],
                      sa + SWZ(row * 128 + koff));
            }
#pragma unroll
            for (int nb = 0; nb < 2; nb++) {
                const int nrow = wn + nb * 16 + ((lane >> 4) << 3) + (lane & 7);
                const int koff = ks * 32 + (((lane >> 3) & 1) << 4);
                ldsm4(rb[nb][0], rb[nb][1], rb[nb][2], rb[nb][3],
                      sb + SWZ(nrow * 128 + koff));
            }
#pragma unroll
            for (int mi = 0; mi < 4; mi++)
#pragma unroll
                for (int nj = 0; nj < 4; nj++)
                    mma16816(acc[mi][nj], ra[mi][0], ra[mi][1], ra[mi][2], ra[mi][3],
                             rb[nj >> 1][(nj & 1) * 2], rb[nj >> 1][(nj & 1) * 2 + 1]);
        }
    }

    // epilogue: + bias, -> bf16
    const int g = lane >> 2, t = lane & 3;
#pragma unroll
    for (int mi = 0; mi < 4; mi++) {
        const int r0 = bm + wm + mi * 16 + g;
#pragma unroll
        for (int nj = 0; nj < 4; nj++) {
            const int col = bn + wn + nj * 8 + 2 * t;
            const float2 bv = *(const float2*)(bias + col);
            __nv_bfloat162 p0 = __floats2bfloat162_rn(acc[mi][nj][0] + bv.x,
                                                      acc[mi][nj][1] + bv.y);
            __nv_bfloat162 p1 = __floats2bfloat162_rn(acc[mi][nj][2] + bv.x,
                                                      acc[mi][nj][3] + bv.y);
            *(__nv_bfloat162*)(C + (size_t)r0 * N_H + col) = p0;
            *(__nv_bfloat162*)(C + (size_t)(r0 + 8) * N_H + col) = p1;
        }
    }
}

// ======================================================================
// Transpose W_dec [1024, 16384] -> g_Wt [16384, 1024]
// ======================================================================
__global__ void transpose_kernel(const float* __restrict__ W) {
    __shared__ float t[32][33];
    const int h0 = blockIdx.x * 32;
    const int d0 = blockIdx.y * 32;
    const int tx = threadIdx.x, ty = threadIdx.y;
#pragma unroll
    for (int i = 0; i < 32; i += 8)
        t[ty + i][tx] = W[(size_t)(d0 + ty + i) * N_H + h0 + tx];
    __syncthreads();
#pragma unroll
    for (int i = 0; i < 32; i += 8)
        g_Wt[(size_t)(h0 + ty + i) * K_D + d0 + tx] = t[tx][ty + i];
}

// ======================================================================
// Fused per-row: candidate selection (approx bf16) -> exact fp32
// recompute -> exact top-32 -> zero+scatter sparse row -> decode row.
// One block of 512 threads per row.
// ======================================================================
__global__ __launch_bounds__(SEL_T) void select_kernel(const float* __restrict__ x,
                                                       const float* __restrict__ W,
                                                       const float* __restrict__ benc,
                                                       const float* __restrict__ bdec,
                                                       float* __restrict__ sparse,
                                                       float* __restrict__ decoded) {
    extern __shared__ unsigned char dyn[];
    uint32_t* sv   = (uint32_t*)dyn;                 // 8192 w (bf16 row)   32KB
    uint32_t* cand = sv + 8192;                      // CAND_SMEM           16KB
    float*    sx   = (float*)(cand + CAND_SMEM);     // 1024 f               4KB
    int*      cidx = (int*)(sx + K_D);               // CANDCAP              2KB
    float*    cval = (float*)(cidx + CANDCAP);       // CANDCAP              2KB
    __shared__ unsigned s_red[16];
    __shared__ unsigned s_cnum, s_emit, s_lo, s_hi, s_sel;
    __shared__ int   s_sidx[KSEL];
    __shared__ float s_sval[KSEL];

    const int tid = threadIdx.x;
    const int row = blockIdx.x;
    const uint4* rp = (const uint4*)(g_encbf + (size_t)row * N_H);

    if (tid == 0) { s_cnum = 0u; s_emit = 0u; s_sel = 0u; }
    if (tid < KSEL) { s_sidx[tid] = 0; s_sval[tid] = 0.f; }

    // x row -> smem (fp32)
    ((float2*)sx)[tid] = ((const float2*)(x + (size_t)row * K_D))[tid];

    // approx row -> smem, max 15-bit key
    unsigned mk = 0u;
#pragma unroll
    for (int j = 0; j < 4; j++) {
        uint4 u = rp[tid + j * SEL_T];
        const int b = (tid + j * SEL_T) * 4;
        sv[b + 0] = u.x; sv[b + 1] = u.y; sv[b + 2] = u.z; sv[b + 3] = u.w;
        mk = max(mk, u.x & 0x7FFFu); mk = max(mk, (u.x >> 16) & 0x7FFFu);
        mk = max(mk, u.y & 0x7FFFu); mk = max(mk, (u.y >> 16) & 0x7FFFu);
        mk = max(mk, u.z & 0x7FFFu); mk = max(mk, (u.z >> 16) & 0x7FFFu);
        mk = max(mk, u.w & 0x7FFFu); mk = max(mk, (u.w >> 16) & 0x7FFFu);
    }
    __syncthreads();
    const unsigned smax = brmax<SEL_T>(mk, s_red);

    // lower bound with count >= KSEL
    unsigned bound = 0u;
    unsigned esub = 1u << 7;
    for (int tries = 0; tries < 16; ++tries) {
        bound = (smax > esub) ? (smax - esub) : 0u;
        unsigned c = 0;
        for (int j = 0; j < 16; j++) {
            const uint32_t u = sv[tid + j * SEL_T];
            c += ((u & 0x7FFFu) >= bound);
            c += (((u >> 16) & 0x7FFFu) >= bound);
        }
        const unsigned tot = brsum<SEL_T>(c, s_red);
        if (tot >= (unsigned)KSEL || bound == 0u) break;
        esub <<= 1;
    }

    // compact (key<<16 | idx)
    for (int j = 0; j < 16; j++) {
        const int w = tid + j * SEL_T;
        const uint32_t u = sv[w];
        const unsigned klo = u & 0x7FFFu, khi = (u >> 16) & 0x7FFFu;
        if (klo >= bound) {
            unsigned p = atomicAdd(&s_cnum, 1u);
            if (p < CAND_SMEM) cand[p] = (klo << 16) | (unsigned)(2 * w);
        }
        if (khi >= bound) {
            unsigned p = atomicAdd(&s_cnum, 1u);
            if (p < CAND_SMEM) cand[p] = (khi << 16) | (unsigned)(2 * w + 1);
        }
    }
    __syncthreads();
    const unsigned cn1 = min(s_cnum, (unsigned)CAND_SMEM);

    // bisect exact 32nd-largest approx key
    if (tid == 0) { s_lo = bound; s_hi = smax; }
    __syncthreads();
    for (int it = 0; it < 16; ++it) {
        const unsigned lo = s_lo, hi = s_hi;
        if (lo >= hi) break;
        const unsigned mid = lo + ((hi - lo + 1) >> 1);
        const unsigned key = mid << 16;
        unsigned c = 0;
        for (unsigned i = tid; i < cn1; i += SEL_T) c += (cand[i] >= key);
        const unsigned t2 = brsum<SEL_T>(c, s_red);
        if (tid == 0) { if (t2 >= (unsigned)KSEL) s_lo = mid; else s_hi = mid - 1; }
        __syncthreads();
    }
    const unsigned short tb = (unsigned short)s_lo;
    float t32f;
    { __nv_bfloat16 h = *(__nv_bfloat16*)&tb; t32f = __bfloat162float(h); }
    const float thr = t32f - (0.0625f + 0.03125f * t32f);

    // emit final candidates
    for (unsigned i = tid; i < cn1; i += SEL_T) {
        const uint32_t pk = cand[i];
        const unsigned short kb = (unsigned short)(pk >> 16);
        __nv_bfloat16 h = *(__nv_bfloat16*)&kb;
        if (__bfloat162float(h) >= thr) {
            unsigned p = atomicAdd(&s_emit, 1u);
            if (p < CANDCAP) cidx[p] = (int)(pk & 0xFFFFu);
        }
    }
    __syncthreads();
    const int cn2 = (int)min(s_emit, (unsigned)CANDCAP);

    // exact fp32 recompute: warp per candidate (16 warps)
    {
        const int wid = tid >> 5, lane = tid & 31;
        const float4* sx4 = (const float4*)sx;
        for (int c = wid; c < cn2; c += 16) {
            const int j = cidx[c];
            const float4* wr = (const float4*)(W + (size_t)j * K_D);
            float s = 0.f;
#pragma unroll
            for (int i = 0; i < 8; i++) {
                const float4 w4 = wr[lane + i * 32];
                const float4 x4 = sx4[lane + i * 32];
                s += w4.x * x4.x + w4.y * x4.y + w4.z * x4.z + w4.w * x4.w;
            }
#pragma unroll
            for (int o = 16; o; o >>= 1) s += __shfl_xor_sync(0xffffffffu, s, o);
            if (lane == 0) cval[c] = s + benc[j];
        }
    }
    __syncthreads();

    // exact top-32 threshold via bisection (narrowed range)
    unsigned mk2 = 0u;
    for (int c = tid; c < cn2; c += SEL_T)
        mk2 = max(mk2, __float_as_uint(fabsf(cval[c])));
    const unsigned smax2 = brmax<SEL_T>(mk2, s_red);
    const float lof = fmaxf(thr - 0.25f, 0.f);
    if (tid == 0) { s_lo = __float_as_uint(lof); s_hi = smax2; }
    __syncthreads();
    for (int it = 0; it < 34; ++it) {
        const unsigned lo = s_lo, hi = s_hi;
        if (lo >= hi) break;
        const unsigned mid = lo + ((hi - lo + 1) >> 1);
        unsigned c = 0;
        for (int i = tid; i < cn2; i += SEL_T)
            c += (__float_as_uint(fabsf(cval[i])) >= mid);
        const unsigned t2 = brsum<SEL_T>(c, s_red);
        if (tid == 0) { if (t2 >= (unsigned)KSEL) s_lo = mid; else s_hi = mid - 1; }
        __syncthreads();
    }
    const unsigned T = s_lo;

    // zero sparse row (coalesced)
    float4* srow4 = (float4*)(sparse + (size_t)row * N_H);
    const float4 z = make_float4(0.f, 0.f, 0.f, 0.f);
#pragma unroll
    for (int j = 0; j < 8; j++) srow4[tid + j * SEL_T] = z;

    // collect winners
    for (int c = tid; c < cn2; c += SEL_T) {
        const float v = cval[c];
        if (__float_as_uint(fabsf(v)) >= T) {
            unsigned p = atomicAdd(&s_sel, 1u);
            if (p < (unsigned)KSEL) { s_sidx[p] = cidx[c]; s_sval[p] = v; }
        }
    }
    __syncthreads();

    // scatter winners over the zeroed row
    if (tid < KSEL) {
        const unsigned nsel = min(s_sel, (unsigned)KSEL);
        if (tid < nsel) sparse[(size_t)row * N_H + s_sidx[tid]] = s_sval[tid];
    }

    // decode: decoded[row, 2t..2t+1] = b_dec + sum_j val_j * Wt[idx_j, 2t..2t+1]
    {
        const int d = 2 * tid;
        float2 acc = *(const float2*)(bdec + d);
#pragma unroll 8
        for (int j = 0; j < KSEL; j++) {
            const float2 w = *(const float2*)(g_Wt + (size_t)s_sidx[j] * K_D + d);
            acc.x += s_sval[j] * w.x;
            acc.y += s_sval[j] * w.y;
        }
        *(float2*)(decoded + (size_t)row * K_D + d) = acc;
    }
}

// ======================================================================
extern "C" void kernel_launch(void* const* d_in, const int* in_sizes, int n_in,
                              void* d_out, int out_size) {
    const float* x     = (const float*)d_in[0];
    const float* W_enc = (const float*)d_in[1];
    const float* b_enc = (const float*)d_in[2];
    const float* W_dec = (const float*)d_in[3];
    const float* b_dec = (const float*)d_in[4];

    float* out = (float*)d_out;
    float* sparse  = out;
    float* decoded = out + (size_t)M_B * N_H;

    __nv_bfloat16 *xb = nullptr, *wb = nullptr, *encbf = nullptr;
    cudaGetSymbolAddress((void**)&xb, g_xb);
    cudaGetSymbolAddress((void**)&wb, g_wb);
    cudaGetSymbolAddress((void**)&encbf, g_encbf);

    // 1) bf16 conversions
    convert_kernel<<<(M_B * K_D / 4) / 256, 256>>>(x, xb);
    convert_kernel<<<(int)(((size_t)N_H * K_D / 4) / 256), 256>>>(W_enc, wb);

    // 2) W_dec transpose
    transpose_kernel<<<dim3(N_H / 32, K_D / 32), dim3(32, 8)>>>(W_dec);

    // 3) approx encoder GEMM (bf16 HMMA, 3-stage, 2 CTA/SM)
    cudaFuncSetAttribute(enc_hmma_kernel, cudaFuncAttributeMaxDynamicSharedMemorySize, 98304);
    enc_hmma_kernel<<<dim3(N_H / 128, M_B / 128), 256, 98304>>>(b_enc, encbf);

    // 4) fused candidates + exact recompute + top-32 + zero/scatter + decode
    const int sel_smem = (8192 + CAND_SMEM) * 4 + K_D * 4 + CANDCAP * 8;  // 57344
    cudaFuncSetAttribute(select_kernel, cudaFuncAttributeMaxDynamicSharedMemorySize, sel_smem);
    select_kernel<<<M_B, SEL_T, sel_smem>>>(x, W_enc, b_enc, b_dec, sparse, decoded);
}

// round 5
// speedup vs baseline: 1.1245x; 1.1245x over previous
#include <cuda_runtime.h>
#include <cuda_bf16.h>
#include <cstdint>

#define M_B 4096
#define N_H 16384
#define K_D 1024
#define KSEL 32
#define NCHUNKS 512          // 16384 / 32 cols per chunk
#define CANDCAP 512

// ---------------- scratch (device globals; no allocation) ----------------
__device__ __nv_bfloat16 g_xb[(size_t)M_B * K_D];      // 8MB   x in bf16
__device__ __nv_bfloat16 g_wb[(size_t)N_H * K_D];      // 33MB  W_enc in bf16
__device__ __nv_bfloat16 g_encbf[(size_t)M_B * N_H];   // 134MB approx enc (bf16)
__device__ unsigned short g_cmax[(size_t)M_B * NCHUNKS]; // 4MB per-(row,chunk) max |bf16| key
__device__ float g_Wt[(size_t)N_H * K_D];              // 64MB  W_dec^T

// ======================= helpers =======================
__device__ __forceinline__ uint32_t smem_u32(const void* p) {
    uint32_t a;
    asm("{ .reg .u64 t; cvta.to.shared.u64 t, %1; cvt.u32.u64 %0, t; }" : "=r"(a) : "l"(p));
    return a;
}
__device__ __forceinline__ void cp16(uint32_t dst, const void* src) {
    asm volatile("cp.async.cg.shared.global [%0], [%1], 16;" :: "r"(dst), "l"(src) : "memory");
}
__device__ __forceinline__ void cp_commit() {
    asm volatile("cp.async.commit_group;" ::: "memory");
}
template <int N> __device__ __forceinline__ void cp_wait() {
    asm volatile("cp.async.wait_group %0;" :: "n"(N) : "memory");
}
__device__ __forceinline__ void ldsm4(uint32_t& r0, uint32_t& r1, uint32_t& r2,
                                      uint32_t& r3, uint32_t a) {
    asm volatile("ldmatrix.sync.aligned.m8n8.x4.shared.b16 {%0,%1,%2,%3}, [%4];"
                 : "=r"(r0), "=r"(r1), "=r"(r2), "=r"(r3) : "r"(a));
}
__device__ __forceinline__ void mma16816(float* d, uint32_t a0, uint32_t a1,
                                         uint32_t a2, uint32_t a3,
                                         uint32_t b0, uint32_t b1) {
    asm volatile("mma.sync.aligned.m16n8k16.row.col.f32.bf16.bf16.f32 "
                 "{%0,%1,%2,%3}, {%4,%5,%6,%7}, {%8,%9}, {%0,%1,%2,%3};"
                 : "+f"(d[0]), "+f"(d[1]), "+f"(d[2]), "+f"(d[3])
                 : "r"(a0), "r"(a1), "r"(a2), "r"(a3), "r"(b0), "r"(b1));
}
#define SWZ(off) ((off) ^ (((off) >> 3) & 0x70))

template <int NT>
__device__ __forceinline__ unsigned brsum(unsigned v, unsigned* s_red) {
    const int tid = threadIdx.x;
#pragma unroll
    for (int o = 16; o; o >>= 1) v += __shfl_xor_sync(0xffffffffu, v, o);
    if ((tid & 31) == 0) s_red[tid >> 5] = v;
    __syncthreads();
    if (tid < 32) {
        unsigned t = (tid < NT / 32) ? s_red[tid] : 0u;
#pragma unroll
        for (int o = 16; o; o >>= 1) t += __shfl_xor_sync(0xffffffffu, t, o);
        if (tid == 0) s_red[0] = t;
    }
    __syncthreads();
    unsigned r = s_red[0];
    __syncthreads();
    return r;
}
template <int NT>
__device__ __forceinline__ unsigned brmax(unsigned v, unsigned* s_red) {
    const int tid = threadIdx.x;
#pragma unroll
    for (int o = 16; o; o >>= 1) v = max(v, __shfl_xor_sync(0xffffffffu, v, o));
    if ((tid & 31) == 0) s_red[tid >> 5] = v;
    __syncthreads();
    if (tid < 32) {
        unsigned t = (tid < NT / 32) ? s_red[tid] : 0u;
#pragma unroll
        for (int o = 16; o; o >>= 1) t = max(t, __shfl_xor_sync(0xffffffffu, t, o));
        if (tid == 0) s_red[0] = t;
    }
    __syncthreads();
    unsigned r = s_red[0];
    __syncthreads();
    return r;
}

// ======================================================================
// fp32 -> bf16 conversion
// ======================================================================
__global__ __launch_bounds__(256) void convert_kernel(const float* __restrict__ src,
                                                      __nv_bfloat16* __restrict__ dst) {
    const size_t g = (size_t)blockIdx.x * 256 + threadIdx.x;
    const float4 v = ((const float4*)src)[g];
    __nv_bfloat162 lo = __floats2bfloat162_rn(v.x, v.y);
    __nv_bfloat162 hi = __floats2bfloat162_rn(v.z, v.w);
    uint32_t a = *(uint32_t*)&lo, b = *(uint32_t*)&hi;
    ((uint2*)dst)[g] = make_uint2(a, b);
}

// ======================================================================
// Approx encoder GEMM (bf16 HMMA), R3-proven 2-stage structure + a
// chunk-max epilogue: per (row, 32-col chunk) max |bf16| key -> g_cmax.
// ======================================================================
__global__ __launch_bounds__(256) void enc_hmma_kernel(const float* __restrict__ bias,
                                                       __nv_bfloat16* __restrict__ C) {
    extern __shared__ __align__(1024) char smem[];   // 2 stages x 32KB
    const int tid = threadIdx.x;
    const int wid = tid >> 5, lane = tid & 31;
    const int bm = blockIdx.y * 128, bn = blockIdx.x * 128;
    const int wm = (wid >> 2) * 64, wn = (wid & 3) * 32;

    float acc[4][4][4];
#pragma unroll
    for (int i = 0; i < 4; i++)
#pragma unroll
        for (int j = 0; j < 4; j++)
#pragma unroll
            for (int q = 0; q < 4; q++) acc[i][j][q] = 0.f;

    const __nv_bfloat16* Abase = g_xb + (size_t)bm * K_D;
    const __nv_bfloat16* Bbase = g_wb + (size_t)bn * K_D;
    auto base_of = [&](int s) { return smem_u32(smem) + s * 32768; };

#define LOAD_TILE(s, kt)                                                          \
    {                                                                             \
        const uint32_t sa = base_of(s);                                           \
        const __nv_bfloat16* Ag = Abase + (kt) * 64;                              \
        const __nv_bfloat16* Bg = Bbase + (kt) * 64;                              \
        _Pragma("unroll")                                                         \
        for (int i = 0; i < 4; i++) {                                             \
            int u = tid + i * 256, row = u >> 3, kb = u & 7;                      \
            cp16(sa + SWZ(row * 128 + kb * 16), Ag + (size_t)row * K_D + kb * 8); \
        }                                                                         \
        _Pragma("unroll")                                                         \
        for (int i = 0; i < 4; i++) {                                             \
            int u = tid + i * 256, row = u >> 3, kb = u & 7;                      \
            cp16(sa + 16384 + SWZ(row * 128 + kb * 16), Bg + (size_t)row * K_D + kb * 8); \
        }                                                                         \
        cp_commit();                                                              \
    }

    LOAD_TILE(0, 0);
    int buf = 0;
    for (int kt = 0; kt < K_D / 64; ++kt) {
        if (kt + 1 < K_D / 64) { LOAD_TILE(buf ^ 1, kt + 1); cp_wait<1>(); }
        else cp_wait<0>();
        __syncthreads();

        const uint32_t sa = base_of(buf);
        const uint32_t sb = sa + 16384;
#pragma unroll
        for (int ks = 0; ks < 4; ks++) {
            uint32_t ra[4][4], rb[2][4];
#pragma unroll
            for (int mi = 0; mi < 4; mi++) {
                const int row = wm + mi * 16 + (lane & 15);
                const int koff = ks * 32 + ((lane >> 4) << 4);
                ldsm4(ra[mi][0], ra[mi][1], ra[mi][2], ra[mi][3],
                      sa + SWZ(row * 128 + koff));
            }
#pragma unroll
            for (int nb = 0; nb < 2; nb++) {
                const int nrow = wn + nb * 16 + ((lane >> 4) << 3) + (lane & 7);
                const int koff = ks * 32 + (((lane >> 3) & 1) << 4);
                ldsm4(rb[nb][0], rb[nb][1], rb[nb][2], rb[nb][3],
                      sb + SWZ(nrow * 128 + koff));
            }
#pragma unroll
            for (int mi = 0; mi < 4; mi++)
#pragma unroll
                for (int nj = 0; nj < 4; nj++)
                    mma16816(acc[mi][nj], ra[mi][0], ra[mi][1], ra[mi][2], ra[mi][3],
                             rb[nj >> 1][(nj & 1) * 2], rb[nj >> 1][(nj & 1) * 2 + 1]);
        }
        __syncthreads();
        buf ^= 1;
    }

    // epilogue: + bias -> bf16 store, and per-(row, 32-col-chunk) max |key|
    const int g = lane >> 2, t = lane & 3;
    const int chunk = (bn >> 5) + (wid & 3);
#pragma unroll
    for (int mi = 0; mi < 4; mi++) {
        const int r0 = bm + wm + mi * 16 + g;
        unsigned k0 = 0u, k1 = 0u;
#pragma unroll
        for (int nj = 0; nj < 4; nj++) {
            const int col = bn + wn + nj * 8 + 2 * t;
            const float2 bv = *(const float2*)(bias + col);
            __nv_bfloat162 p0 = __floats2bfloat162_rn(acc[mi][nj][0] + bv.x,
                                                      acc[mi][nj][1] + bv.y);
            __nv_bfloat162 p1 = __floats2bfloat162_rn(acc[mi][nj][2] + bv.x,
                                                      acc[mi][nj][3] + bv.y);
            const uint32_t u0 = *(uint32_t*)&p0, u1 = *(uint32_t*)&p1;
            k0 = max(k0, max(u0 & 0x7FFFu, (u0 >> 16) & 0x7FFFu));
            k1 = max(k1, max(u1 & 0x7FFFu, (u1 >> 16) & 0x7FFFu));
            *(__nv_bfloat162*)(C + (size_t)r0 * N_H + col) = p0;
            *(__nv_bfloat162*)(C + (size_t)(r0 + 8) * N_H + col) = p1;
        }
        // quad reduce across t (covers all 32 chunk columns)
        k0 = max(k0, __shfl_xor_sync(0xffffffffu, k0, 1));
        k0 = max(k0, __shfl_xor_sync(0xffffffffu, k0, 2));
        k1 = max(k1, __shfl_xor_sync(0xffffffffu, k1, 1));
        k1 = max(k1, __shfl_xor_sync(0xffffffffu, k1, 2));
        if (t == 0) {
            g_cmax[(size_t)r0 * NCHUNKS + chunk] = (unsigned short)k0;
            g_cmax[(size_t)(r0 + 8) * NCHUNKS + chunk] = (unsigned short)k1;
        }
    }
}

// ======================================================================
// Transpose W_dec [1024, 16384] -> g_Wt [16384, 1024]
// ======================================================================
__global__ void transpose_kernel(const float* __restrict__ W) {
    __shared__ float t[32][33];
    const int h0 = blockIdx.x * 32;
    const int d0 = blockIdx.y * 32;
    const int tx = threadIdx.x, ty = threadIdx.y;
#pragma unroll
    for (int i = 0; i < 32; i += 8)
        t[ty + i][tx] = W[(size_t)(d0 + ty + i) * N_H + h0 + tx];
    __syncthreads();
#pragma unroll
    for (int i = 0; i < 32; i += 8)
        g_Wt[(size_t)(h0 + ty + i) * K_D + d0 + tx] = t[tx][ty + i];
}

// ======================================================================
// Fused per-row tail (256 threads, ~11KB smem, high occupancy):
//  1. 32nd-largest of 512 chunk-max keys  (tau_sub <= 32nd of approx row)
//  2. thr = tau_sub - margin; inspect only chunks with cmax >= thr
//  3. exact fp32 recompute of candidates; exact top-32 via key bisection
//  4. zero + scatter sparse row; decode row
// ======================================================================
__global__ __launch_bounds__(256) void select_kernel(const float* __restrict__ x,
                                                     const float* __restrict__ W,
                                                     const float* __restrict__ benc,
                                                     const float* __restrict__ bdec,
                                                     float* __restrict__ sparse,
                                                     float* __restrict__ decoded) {
    __shared__ float sx[K_D];                    // 4KB x row
    __shared__ unsigned short scmax[NCHUNKS];    // 1KB
    __shared__ unsigned short achunk[NCHUNKS];   // 1KB active chunk ids
    __shared__ int   cidx[CANDCAP];              // 2KB
    __shared__ float cval[CANDCAP];              // 2KB
    __shared__ unsigned s_red[8];
    __shared__ unsigned s_na, s_emit, s_sel, s_lo, s_hi;
    __shared__ int   s_sidx[KSEL];
    __shared__ float s_sval[KSEL];

    const int tid = threadIdx.x;
    const int row = blockIdx.x;
    const int wid = tid >> 5, lane = tid & 31;

    if (tid == 0) { s_na = 0u; s_emit = 0u; s_sel = 0u; }
    if (tid < KSEL) { s_sidx[tid] = 0; s_sval[tid] = 0.f; }

    // x row -> smem
    ((float4*)sx)[tid] = ((const float4*)(x + (size_t)row * K_D))[tid];

    // chunk maxes -> smem, block max
    const uint32_t* cm32 = (const uint32_t*)(g_cmax + (size_t)row * NCHUNKS);
    unsigned mk = 0u;
    {
        const uint32_t u = cm32[tid];
        ((uint32_t*)scmax)[tid] = u;
        mk = max(mk, max(u & 0xFFFFu, u >> 16));
    }
    __syncthreads();
    const unsigned smax = brmax<256>(mk, s_red);

    // exact 32nd-largest chunk-max key (15-bit bisection, 512 values)
    if (tid == 0) { s_lo = 0u; s_hi = smax; }
    __syncthreads();
    for (int it = 0; it < 15; ++it) {
        const unsigned lo = s_lo, hi = s_hi;
        if (lo >= hi) break;
        const unsigned mid = lo + ((hi - lo + 1) >> 1);
        const uint32_t u = ((uint32_t*)scmax)[tid];
        unsigned c = ((u & 0xFFFFu) >= mid) + ((u >> 16) >= mid);
        const unsigned t2 = brsum<256>(c, s_red);
        if (tid == 0) { if (t2 >= (unsigned)KSEL) s_lo = mid; else s_hi = mid - 1; }
        __syncthreads();
    }
    const unsigned short tsub = (unsigned short)s_lo;
    float tsubf;
    { __nv_bfloat16 h = *(__nv_bfloat16*)&tsub; tsubf = __bfloat162float(h); }
    const float thrf = tsubf - (0.0625f + 0.03125f * tsubf);   // proven margin
    unsigned thrkey;
    {
        float tc = fmaxf(thrf, 0.f);
        __nv_bfloat16 h = __float2bfloat16_rz(tc);              // round down (>=0)
        thrkey = *(unsigned short*)&h;
    }

    // active chunks
    {
        const uint32_t u = ((uint32_t*)scmax)[tid];
        if ((u & 0xFFFFu) >= thrkey) {
            unsigned p = atomicAdd(&s_na, 1u);
            achunk[p] = (unsigned short)(2 * tid);
        }
        if ((u >> 16) >= thrkey) {
            unsigned p = atomicAdd(&s_na, 1u);
            achunk[p] = (unsigned short)(2 * tid + 1);
        }
    }
    __syncthreads();
    const int na = (int)s_na;

    // inspect active chunks: warp i handles chunks i, i+8, ... (16 lanes/chunk)
    const uint32_t* erow = (const uint32_t*)(g_encbf + (size_t)row * N_H);
    for (int i = wid; i < na; i += 8) {
        const int c = achunk[i];
        if (lane < 16) {
            const uint32_t u = erow[c * 16 + lane];
            const unsigned klo = u & 0x7FFFu, khi = (u >> 16) & 0x7FFFu;
            if (klo >= thrkey) {
                unsigned p = atomicAdd(&s_emit, 1u);
                if (p < CANDCAP) cidx[p] = c * 32 + 2 * lane;
            }
            if (khi >= thrkey) {
                unsigned p = atomicAdd(&s_emit, 1u);
                if (p < CANDCAP) cidx[p] = c * 32 + 2 * lane + 1;
            }
        }
    }
    __syncthreads();
    const int cn = (int)min(s_emit, (unsigned)CANDCAP);

    // exact fp32 recompute: warp per candidate
    {
        const float4* sx4 = (const float4*)sx;
        for (int c = wid; c < cn; c += 8) {
            const int j = cidx[c];
            const float4* wr = (const float4*)(W + (size_t)j * K_D);
            float s = 0.f;
#pragma unroll
            for (int i = 0; i < 8; i++) {
                const float4 w4 = wr[lane + i * 32];
                const float4 x4 = sx4[lane + i * 32];
                s += w4.x * x4.x + w4.y * x4.y + w4.z * x4.z + w4.w * x4.w;
            }
#pragma unroll
            for (int o = 16; o; o >>= 1) s += __shfl_xor_sync(0xffffffffu, s, o);
            if (lane == 0) cval[c] = s + benc[j];
        }
    }
    __syncthreads();

    // exact top-32 threshold among candidates (narrowed fp32-key bisection)
    unsigned mk2 = 0u;
    for (int c = tid; c < cn; c += 256)
        mk2 = max(mk2, __float_as_uint(fabsf(cval[c])));
    const unsigned smax2 = brmax<256>(mk2, s_red);
    if (tid == 0) { s_lo = __float_as_uint(fmaxf(thrf, 0.f)); s_hi = smax2; }
    __syncthreads();
    for (int it = 0; it < 34; ++it) {
        const unsigned lo = s_lo, hi = s_hi;
        if (lo >= hi) break;
        const unsigned mid = lo + ((hi - lo + 1) >> 1);
        unsigned c = 0;
        for (int i = tid; i < cn; i += 256)
            c += (__float_as_uint(fabsf(cval[i])) >= mid);
        const unsigned t2 = brsum<256>(c, s_red);
        if (tid == 0) { if (t2 >= (unsigned)KSEL) s_lo = mid; else s_hi = mid - 1; }
        __syncthreads();
    }
    const unsigned T = s_lo;

    // zero sparse row (coalesced 64KB)
    float4* srow4 = (float4*)(sparse + (size_t)row * N_H);
    const float4 z = make_float4(0.f, 0.f, 0.f, 0.f);
#pragma unroll
    for (int j = 0; j < 16; j++) srow4[tid + j * 256] = z;

    // collect winners
    for (int c = tid; c < cn; c += 256) {
        const float v = cval[c];
        if (__float_as_uint(fabsf(v)) >= T) {
            unsigned p = atomicAdd(&s_sel, 1u);
            if (p < (unsigned)KSEL) { s_sidx[p] = cidx[c]; s_sval[p] = v; }
        }
    }
    __syncthreads();

    // scatter winners
    if (tid < KSEL && tid < (int)min(s_sel, (unsigned)KSEL))
        sparse[(size_t)row * N_H + s_sidx[tid]] = s_sval[tid];

    // decode row: 256 threads x float4 (proven 34us pattern)
    {
        const float4* Wt4 = (const float4*)g_Wt;
        float4 acc = ((const float4*)bdec)[tid];
#pragma unroll 8
        for (int j = 0; j < KSEL; j++) {
            const float4 w = Wt4[(size_t)s_sidx[j] * (K_D / 4) + tid];
            const float s = s_sval[j];
            acc.x += s * w.x; acc.y += s * w.y; acc.z += s * w.z; acc.w += s * w.w;
        }
        ((float4*)(decoded + (size_t)row * K_D))[tid] = acc;
    }
}

// ======================================================================
extern "C" void kernel_launch(void* const* d_in, const int* in_sizes, int n_in,
                              void* d_out, int out_size) {
    const float* x     = (const float*)d_in[0];
    const float* W_enc = (const float*)d_in[1];
    const float* b_enc = (const float*)d_in[2];
    const float* W_dec = (const float*)d_in[3];
    const float* b_dec = (const float*)d_in[4];

    float* out = (float*)d_out;
    float* sparse  = out;
    float* decoded = out + (size_t)M_B * N_H;

    __nv_bfloat16 *xb = nullptr, *wb = nullptr, *encbf = nullptr;
    cudaGetSymbolAddress((void**)&xb, g_xb);
    cudaGetSymbolAddress((void**)&wb, g_wb);
    cudaGetSymbolAddress((void**)&encbf, g_encbf);

    // 1) bf16 conversions
    convert_kernel<<<(M_B * K_D / 4) / 256, 256>>>(x, xb);
    convert_kernel<<<(int)(((size_t)N_H * K_D / 4) / 256), 256>>>(W_enc, wb);

    // 2) W_dec transpose
    transpose_kernel<<<dim3(N_H / 32, K_D / 32), dim3(32, 8)>>>(W_dec);

    // 3) approx encoder GEMM (R3 structure) + chunk-max epilogue
    cudaFuncSetAttribute(enc_hmma_kernel, cudaFuncAttributeMaxDynamicSharedMemorySize, 65536);
    enc_hmma_kernel<<<dim3(N_H / 128, M_B / 128), 256, 65536>>>(b_enc, encbf);

    // 4) fused tail: chunk-max select + exact recompute + top-32 + zero/scatter + decode
    select_kernel<<<M_B, 256>>>(x, W_enc, b_enc, b_dec, sparse, decoded);
}

// round 6
// speedup vs baseline: 1.1977x; 1.0650x over previous
#include <cuda_runtime.h>
#include <cuda_bf16.h>
#include <cstdint>

#define M_B 4096
#define N_H 16384
#define K_D 1024
#define KSEL 32
#define NCHUNKS 512          // 16384 / 32 cols per chunk
#define CANDCAP 512

// ---------------- scratch (device globals; no allocation) ----------------
__device__ __nv_bfloat16 g_xb[(size_t)M_B * K_D];        // 8MB   x in bf16
__device__ __nv_bfloat16 g_wb[(size_t)N_H * K_D];        // 33MB  W_enc in bf16
__device__ __nv_bfloat16 g_encbf[(size_t)M_B * N_H];     // 134MB approx enc (bf16)
__device__ unsigned short g_cmax[(size_t)M_B * NCHUNKS]; // 4MB chunk max |bf16| keys
__device__ float g_Wt[(size_t)N_H * K_D];                // 64MB  W_dec^T

// ======================= helpers =======================
__device__ __forceinline__ uint32_t smem_u32(const void* p) {
    uint32_t a;
    asm("{ .reg .u64 t; cvta.to.shared.u64 t, %1; cvt.u32.u64 %0, t; }" : "=r"(a) : "l"(p));
    return a;
}
__device__ __forceinline__ void cp16(uint32_t dst, const void* src) {
    asm volatile("cp.async.cg.shared.global [%0], [%1], 16;" :: "r"(dst), "l"(src) : "memory");
}
__device__ __forceinline__ void cp_commit() {
    asm volatile("cp.async.commit_group;" ::: "memory");
}
template <int N> __device__ __forceinline__ void cp_wait() {
    asm volatile("cp.async.wait_group %0;" :: "n"(N) : "memory");
}
__device__ __forceinline__ void ldsm4(uint32_t& r0, uint32_t& r1, uint32_t& r2,
                                      uint32_t& r3, uint32_t a) {
    asm volatile("ldmatrix.sync.aligned.m8n8.x4.shared.b16 {%0,%1,%2,%3}, [%4];"
                 : "=r"(r0), "=r"(r1), "=r"(r2), "=r"(r3) : "r"(a));
}
__device__ __forceinline__ void mma16816(float* d, uint32_t a0, uint32_t a1,
                                         uint32_t a2, uint32_t a3,
                                         uint32_t b0, uint32_t b1) {
    asm volatile("mma.sync.aligned.m16n8k16.row.col.f32.bf16.bf16.f32 "
                 "{%0,%1,%2,%3}, {%4,%5,%6,%7}, {%8,%9}, {%0,%1,%2,%3};"
                 : "+f"(d[0]), "+f"(d[1]), "+f"(d[2]), "+f"(d[3])
                 : "r"(a0), "r"(a1), "r"(a2), "r"(a3), "r"(b0), "r"(b1));
}
#define SWZ(off) ((off) ^ (((off) >> 3) & 0x70))

// ======================================================================
// fp32 -> bf16 conversion
// ======================================================================
__global__ __launch_bounds__(256) void convert_kernel(const float* __restrict__ src,
                                                      __nv_bfloat16* __restrict__ dst) {
    const size_t g = (size_t)blockIdx.x * 256 + threadIdx.x;
    const float4 v = ((const float4*)src)[g];
    __nv_bfloat162 lo = __floats2bfloat162_rn(v.x, v.y);
    __nv_bfloat162 hi = __floats2bfloat162_rn(v.z, v.w);
    uint32_t a = *(uint32_t*)&lo, b = *(uint32_t*)&hi;
    ((uint2*)dst)[g] = make_uint2(a, b);
}

// ======================================================================
// Approx encoder GEMM (bf16 HMMA): CTA 128x128, 4 warps, warp tile 64x64
// (MMA:ldsm ratio 4 -> lower L1 pressure). 2-stage cp.async (R3-proven
// pipeline). Epilogue: bias + bf16 store, chunk-max keys, AND zero-fill
// of this CTA's sparse-output tile.
// ======================================================================
__global__ __launch_bounds__(128, 2) void enc_hmma_kernel(const float* __restrict__ bias,
                                                          __nv_bfloat16* __restrict__ C,
                                                          float* __restrict__ sparse) {
    extern __shared__ __align__(1024) char smem[];   // 2 stages x 32KB
    const int tid = threadIdx.x;
    const int wid = tid >> 5, lane = tid & 31;
    const int bm = blockIdx.y * 128, bn = blockIdx.x * 128;
    const int wm = (wid >> 1) * 64, wn = (wid & 1) * 64;

    float acc[4][8][4];
#pragma unroll
    for (int i = 0; i < 4; i++)
#pragma unroll
        for (int j = 0; j < 8; j++)
#pragma unroll
            for (int q = 0; q < 4; q++) acc[i][j][q] = 0.f;

    const __nv_bfloat16* Abase = g_xb + (size_t)bm * K_D;
    const __nv_bfloat16* Bbase = g_wb + (size_t)bn * K_D;
    auto base_of = [&](int s) { return smem_u32(smem) + s * 32768; };

#define LOAD_TILE(s, kt)                                                          \
    {                                                                             \
        const uint32_t sa = base_of(s);                                           \
        const __nv_bfloat16* Ag = Abase + (kt) * 64;                              \
        const __nv_bfloat16* Bg = Bbase + (kt) * 64;                              \
        _Pragma("unroll")                                                         \
        for (int i = 0; i < 8; i++) {                                             \
            int u = tid + i * 128, row = u >> 3, kb = u & 7;                      \
            cp16(sa + SWZ(row * 128 + kb * 16), Ag + (size_t)row * K_D + kb * 8); \
        }                                                                         \
        _Pragma("unroll")                                                         \
        for (int i = 0; i < 8; i++) {                                             \
            int u = tid + i * 128, row = u >> 3, kb = u & 7;                      \
            cp16(sa + 16384 + SWZ(row * 128 + kb * 16), Bg + (size_t)row * K_D + kb * 8); \
        }                                                                         \
        cp_commit();                                                              \
    }

    LOAD_TILE(0, 0);
    int buf = 0;
    for (int kt = 0; kt < K_D / 64; ++kt) {
        if (kt + 1 < K_D / 64) { LOAD_TILE(buf ^ 1, kt + 1); cp_wait<1>(); }
        else cp_wait<0>();
        __syncthreads();

        const uint32_t sa = base_of(buf);
        const uint32_t sb = sa + 16384;
#pragma unroll
        for (int ks = 0; ks < 4; ks++) {
            uint32_t ra[4][4], rb[4][4];
#pragma unroll
            for (int mi = 0; mi < 4; mi++) {
                const int row = wm + mi * 16 + (lane & 15);
                const int koff = ks * 32 + ((lane >> 4) << 4);
                ldsm4(ra[mi][0], ra[mi][1], ra[mi][2], ra[mi][3],
                      sa + SWZ(row * 128 + koff));
            }
#pragma unroll
            for (int nb = 0; nb < 4; nb++) {
                const int nrow = wn + nb * 16 + ((lane >> 4) << 3) + (lane & 7);
                const int koff = ks * 32 + (((lane >> 3) & 1) << 4);
                ldsm4(rb[nb][0], rb[nb][1], rb[nb][2], rb[nb][3],
                      sb + SWZ(nrow * 128 + koff));
            }
#pragma unroll
            for (int mi = 0; mi < 4; mi++)
#pragma unroll
                for (int nj = 0; nj < 8; nj++)
                    mma16816(acc[mi][nj], ra[mi][0], ra[mi][1], ra[mi][2], ra[mi][3],
                             rb[nj >> 1][(nj & 1) * 2], rb[nj >> 1][(nj & 1) * 2 + 1]);
        }
        __syncthreads();
        buf ^= 1;
    }

    // epilogue: + bias -> bf16 store; chunk-max keys (2 chunks per warp span)
    const int g = lane >> 2, t = lane & 3;
    const int chunk0 = ((bn + wn) >> 5);
#pragma unroll
    for (int mi = 0; mi < 4; mi++) {
        const int r0 = bm + wm + mi * 16 + g;
        unsigned ka0 = 0u, ka1 = 0u, kb0 = 0u, kb1 = 0u;  // chunkA/B x rows r0,r0+8
#pragma unroll
        for (int nj = 0; nj < 8; nj++) {
            const int col = bn + wn + nj * 8 + 2 * t;
            const float2 bv = *(const float2*)(bias + col);
            __nv_bfloat162 p0 = __floats2bfloat162_rn(acc[mi][nj][0] + bv.x,
                                                      acc[mi][nj][1] + bv.y);
            __nv_bfloat162 p1 = __floats2bfloat162_rn(acc[mi][nj][2] + bv.x,
                                                      acc[mi][nj][3] + bv.y);
            const uint32_t u0 = *(uint32_t*)&p0, u1 = *(uint32_t*)&p1;
            const unsigned m0 = max(u0 & 0x7FFFu, (u0 >> 16) & 0x7FFFu);
            const unsigned m1 = max(u1 & 0x7FFFu, (u1 >> 16) & 0x7FFFu);
            if (nj < 4) { ka0 = max(ka0, m0); ka1 = max(ka1, m1); }
            else        { kb0 = max(kb0, m0); kb1 = max(kb1, m1); }
            *(__nv_bfloat162*)(C + (size_t)r0 * N_H + col) = p0;
            *(__nv_bfloat162*)(C + (size_t)(r0 + 8) * N_H + col) = p1;
        }
        ka0 = max(ka0, __shfl_xor_sync(0xffffffffu, ka0, 1));
        ka0 = max(ka0, __shfl_xor_sync(0xffffffffu, ka0, 2));
        ka1 = max(ka1, __shfl_xor_sync(0xffffffffu, ka1, 1));
        ka1 = max(ka1, __shfl_xor_sync(0xffffffffu, ka1, 2));
        kb0 = max(kb0, __shfl_xor_sync(0xffffffffu, kb0, 1));
        kb0 = max(kb0, __shfl_xor_sync(0xffffffffu, kb0, 2));
        kb1 = max(kb1, __shfl_xor_sync(0xffffffffu, kb1, 1));
        kb1 = max(kb1, __shfl_xor_sync(0xffffffffu, kb1, 2));
        if (t == 0) {
            g_cmax[(size_t)r0 * NCHUNKS + chunk0] = (unsigned short)ka0;
            g_cmax[(size_t)(r0 + 8) * NCHUNKS + chunk0] = (unsigned short)ka1;
            g_cmax[(size_t)r0 * NCHUNKS + chunk0 + 1] = (unsigned short)kb0;
            g_cmax[(size_t)(r0 + 8) * NCHUNKS + chunk0 + 1] = (unsigned short)kb1;
        }
    }

    // zero-fill this CTA's sparse tile (128 x 128 fp32, streamed to DRAM)
    {
        const float4 z = make_float4(0.f, 0.f, 0.f, 0.f);
#pragma unroll
        for (int i = tid; i < 128 * 32; i += 128) {
            const int r = i >> 5, c4 = i & 31;
            ((float4*)(sparse + (size_t)(bm + r) * N_H + bn))[c4] = z;
        }
    }
}

// ======================================================================
// Transpose W_dec [1024, 16384] -> g_Wt [16384, 1024]
// ======================================================================
__global__ void transpose_kernel(const float* __restrict__ W) {
    __shared__ float t[32][33];
    const int h0 = blockIdx.x * 32;
    const int d0 = blockIdx.y * 32;
    const int tx = threadIdx.x, ty = threadIdx.y;
#pragma unroll
    for (int i = 0; i < 32; i += 8)
        t[ty + i][tx] = W[(size_t)(d0 + ty + i) * N_H + h0 + tx];
    __syncthreads();
#pragma unroll
    for (int i = 0; i < 32; i += 8)
        g_Wt[(size_t)(h0 + ty + i) * K_D + d0 + tx] = t[tx][ty + i];
}

// ======================================================================
// Fused per-row tail (256 threads, ~11KB smem, 8 blocks/SM, only ~5
// block-wide syncs; both bisections are single-warp shfl-only):
//  1. warp0: 32nd-largest of 512 chunk-max keys -> margin threshold
//  2. all: inspect active chunks, emit candidates
//  3. 8 warps: exact fp32 recompute of candidates
//  4. warp0: exact top-32 threshold + winner collection
//  5. all: scatter winners (row pre-zeroed by GEMM) + decode row
// ======================================================================
__global__ __launch_bounds__(256) void select_kernel(const float* __restrict__ x,
                                                     const float* __restrict__ W,
                                                     const float* __restrict__ benc,
                                                     const float* __restrict__ bdec,
                                                     float* __restrict__ sparse,
                                                     float* __restrict__ decoded) {
    __shared__ float sx[K_D];                    // 4KB
    __shared__ unsigned short scmax[NCHUNKS];    // 1KB
    __shared__ unsigned short achunk[NCHUNKS];   // 1KB
    __shared__ int   cidx[CANDCAP];              // 2KB
    __shared__ float cval[CANDCAP];              // 2KB
    __shared__ unsigned s_na, s_emit, s_sel, s_thrkey;
    __shared__ int   s_sidx[KSEL];
    __shared__ float s_sval[KSEL];

    const int tid = threadIdx.x;
    const int row = blockIdx.x;
    const int wid = tid >> 5, lane = tid & 31;

    if (tid == 0) { s_na = 0u; s_emit = 0u; s_sel = 0u; }
    if (tid < KSEL) { s_sidx[tid] = 0; s_sval[tid] = 0.f; }

    ((float4*)sx)[tid] = ((const float4*)(x + (size_t)row * K_D))[tid];
    ((uint32_t*)scmax)[tid] = ((const uint32_t*)(g_cmax + (size_t)row * NCHUNKS))[tid];
    __syncthreads();

    // ---- warp0: chunk-max bisection (15-bit keys), shfl-only ----
    float thrf_w0 = 0.f;
    if (wid == 0) {
        unsigned k[16];
#pragma unroll
        for (int i = 0; i < 16; i++) k[i] = scmax[lane + 32 * i];
        unsigned mx = 0u;
#pragma unroll
        for (int i = 0; i < 16; i++) mx = max(mx, k[i]);
#pragma unroll
        for (int o = 16; o; o >>= 1) mx = max(mx, __shfl_xor_sync(0xffffffffu, mx, o));
        unsigned lo = 0u, hi = mx;
#pragma unroll
        for (int it = 0; it < 15; ++it) {
            const unsigned mid = lo + ((hi - lo + 1) >> 1);
            if (lo >= hi) break;
            unsigned c = 0;
#pragma unroll
            for (int i = 0; i < 16; i++) c += (k[i] >= mid);
#pragma unroll
            for (int o = 16; o; o >>= 1) c += __shfl_xor_sync(0xffffffffu, c, o);
            if (c >= (unsigned)KSEL) lo = mid; else hi = mid - 1;
        }
        const unsigned short tsub = (unsigned short)lo;
        float tsubf;
        { __nv_bfloat16 h = *(__nv_bfloat16*)&tsub; tsubf = __bfloat162float(h); }
        thrf_w0 = fmaxf(tsubf - (0.0625f + 0.03125f * tsubf), 0.f);
        unsigned thrkey;
        { __nv_bfloat16 h = __float2bfloat16_rz(thrf_w0); thrkey = *(unsigned short*)&h; }
        if (lane == 0) s_thrkey = thrkey;
        // active chunks
#pragma unroll
        for (int i = 0; i < 16; i++) {
            if (k[i] >= thrkey) {
                unsigned p = atomicAdd(&s_na, 1u);
                achunk[p] = (unsigned short)(lane + 32 * i);
            }
        }
    }
    __syncthreads();
    const unsigned thrkey = s_thrkey;
    const int na = (int)s_na;

    // ---- candidate scan of active chunks ----
    const uint32_t* erow = (const uint32_t*)(g_encbf + (size_t)row * N_H);
    for (int i = wid; i < na; i += 8) {
        const int c = achunk[i];
        if (lane < 16) {
            const uint32_t u = erow[c * 16 + lane];
            const unsigned klo = u & 0x7FFFu, khi = (u >> 16) & 0x7FFFu;
            if (klo >= thrkey) {
                unsigned p = atomicAdd(&s_emit, 1u);
                if (p < CANDCAP) cidx[p] = c * 32 + 2 * lane;
            }
            if (khi >= thrkey) {
                unsigned p = atomicAdd(&s_emit, 1u);
                if (p < CANDCAP) cidx[p] = c * 32 + 2 * lane + 1;
            }
        }
    }
    __syncthreads();
    const int cn = (int)min(s_emit, (unsigned)CANDCAP);

    // ---- exact fp32 recompute: warp per candidate ----
    {
        const float4* sx4 = (const float4*)sx;
        for (int c = wid; c < cn; c += 8) {
            const int j = cidx[c];
            const float4* wr = (const float4*)(W + (size_t)j * K_D);
            float s = 0.f;
#pragma unroll
            for (int i = 0; i < 8; i++) {
                const float4 w4 = wr[lane + i * 32];
                const float4 x4 = sx4[lane + i * 32];
                s += w4.x * x4.x + w4.y * x4.y + w4.z * x4.z + w4.w * x4.w;
            }
#pragma unroll
            for (int o = 16; o; o >>= 1) s += __shfl_xor_sync(0xffffffffu, s, o);
            if (lane == 0) cval[c] = s + benc[j];
        }
    }
    __syncthreads();

    // ---- warp0: exact top-32 among candidates (fp32 keys, shfl-only) ----
    if (wid == 0) {
        unsigned kk[16];
#pragma unroll
        for (int j = 0; j < 16; j++) {
            const int idx = lane + 32 * j;
            kk[j] = (idx < cn) ? __float_as_uint(fabsf(cval[idx])) : 0u;
        }
        unsigned mx = 0u;
#pragma unroll
        for (int j = 0; j < 16; j++) mx = max(mx, kk[j]);
#pragma unroll
        for (int o = 16; o; o >>= 1) mx = max(mx, __shfl_xor_sync(0xffffffffu, mx, o));
        unsigned lo = __float_as_uint(thrf_w0), hi = mx;
        for (int it = 0; it < 32; ++it) {
            if (lo >= hi) break;
            const unsigned mid = lo + ((hi - lo + 1) >> 1);
            unsigned c = 0;
#pragma unroll
            for (int j = 0; j < 16; j++) c += (kk[j] >= mid);
#pragma unroll
            for (int o = 16; o; o >>= 1) c += __shfl_xor_sync(0xffffffffu, c, o);
            if (c >= (unsigned)KSEL) lo = mid; else hi = mid - 1;
        }
        const unsigned T = lo;
#pragma unroll
        for (int j = 0; j < 16; j++) {
            const int idx = lane + 32 * j;
            if (idx < cn && kk[j] >= T) {
                unsigned p = atomicAdd(&s_sel, 1u);
                if (p < (unsigned)KSEL) { s_sidx[p] = cidx[idx]; s_sval[p] = cval[idx]; }
            }
        }
    }
    __syncthreads();

    // ---- scatter winners (row already zeroed by GEMM epilogue) ----
    if (tid < KSEL && tid < (int)min(s_sel, (unsigned)KSEL))
        sparse[(size_t)row * N_H + s_sidx[tid]] = s_sval[tid];

    // ---- decode row ----
    {
        const float4* Wt4 = (const float4*)g_Wt;
        float4 acc = ((const float4*)bdec)[tid];
#pragma unroll 8
        for (int j = 0; j < KSEL; j++) {
            const float4 w = Wt4[(size_t)s_sidx[j] * (K_D / 4) + tid];
            const float s = s_sval[j];
            acc.x += s * w.x; acc.y += s * w.y; acc.z += s * w.z; acc.w += s * w.w;
        }
        ((float4*)(decoded + (size_t)row * K_D))[tid] = acc;
    }
}

// ======================================================================
extern "C" void kernel_launch(void* const* d_in, const int* in_sizes, int n_in,
                              void* d_out, int out_size) {
    const float* x     = (const float*)d_in[0];
    const float* W_enc = (const float*)d_in[1];
    const float* b_enc = (const float*)d_in[2];
    const float* W_dec = (const float*)d_in[3];
    const float* b_dec = (const float*)d_in[4];

    float* out = (float*)d_out;
    float* sparse  = out;
    float* decoded = out + (size_t)M_B * N_H;

    __nv_bfloat16 *xb = nullptr, *wb = nullptr, *encbf = nullptr;
    cudaGetSymbolAddress((void**)&xb, g_xb);
    cudaGetSymbolAddress((void**)&wb, g_wb);
    cudaGetSymbolAddress((void**)&encbf, g_encbf);

    // 1) bf16 conversions
    convert_kernel<<<(M_B * K_D / 4) / 256, 256>>>(x, xb);
    convert_kernel<<<(int)(((size_t)N_H * K_D / 4) / 256), 256>>>(W_enc, wb);

    // 2) W_dec transpose
    transpose_kernel<<<dim3(N_H / 32, K_D / 32), dim3(32, 8)>>>(W_dec);

    // 3) approx encoder GEMM (64x64 warp tiles) + chunk-max + zero-fill epilogues
    cudaFuncSetAttribute(enc_hmma_kernel, cudaFuncAttributeMaxDynamicSharedMemorySize, 65536);
    enc_hmma_kernel<<<dim3(N_H / 128, M_B / 128), 128, 65536>>>(b_enc, encbf, sparse);

    // 4) fused tail: select + exact recompute + top-32 + scatter + decode
    select_kernel<<<M_B, 256>>>(x, W_enc, b_enc, b_dec, sparse, decoded);
}